// round 15
// baseline (speedup 1.0000x reference)
#include <cuda_runtime.h>
#include <cuda_bf16.h>
#include <math.h>
#include <stdint.h>

namespace {
constexpr int B_   = 32;
constexpr int N_   = 512;
constexpr int C_   = 768;
constexpr int H_   = 12;
constexpr int D_   = 64;
constexpr int HID_ = 3072;
constexpr int M_   = B_ * N_;   // 16384
constexpr int BH_  = B_ * H_;   // 384
}

// fp32 scratch
__device__ float g_xres[M_ * C_];
// bf16 hi/lo planes
__device__ __nv_bfloat16 g_h_hi[M_ * C_],      g_h_lo[M_ * C_];
__device__ __nv_bfloat16 g_qkv_hi[M_ * 3 * C_],g_qkv_lo[M_ * 3 * C_];
__device__ __nv_bfloat16 g_o_hi[M_ * C_],      g_o_lo[M_ * C_];
__device__ __nv_bfloat16 g_f1_hi[M_ * HID_],   g_f1_lo[M_ * HID_];
__device__ __nv_bfloat16 g_qkvw_hi[3 * C_ * C_], g_qkvw_lo[3 * C_ * C_];
__device__ __nv_bfloat16 g_projw_hi[C_ * C_],  g_projw_lo[C_ * C_];
__device__ __nv_bfloat16 g_fc1w_hi[HID_ * C_], g_fc1w_lo[HID_ * C_];
__device__ __nv_bfloat16 g_fc2w_hi[C_ * HID_], g_fc2w_lo[C_ * HID_];

// ---------------------------------------------------------------------------
// helpers
// ---------------------------------------------------------------------------
__device__ __forceinline__ uint32_t smem_u32(const void* p) {
    uint32_t a;
    asm("{ .reg .u64 t; cvta.to.shared.u64 t, %1; cvt.u32.u64 %0, t; }" : "=r"(a) : "l"(p));
    return a;
}
#define CP_ASYNC8(dst, src) \
    asm volatile("cp.async.ca.shared.global [%0], [%1], 8;" :: "r"(dst), "l"(src))
#define CP_ASYNC16(dst, src) \
    asm volatile("cp.async.cg.shared.global [%0], [%1], 16;" :: "r"(dst), "l"(src))
#define CP_COMMIT() asm volatile("cp.async.commit_group;" ::: "memory")
#define CP_WAIT1()  asm volatile("cp.async.wait_group 1;" ::: "memory")

#define LDSM_X4(r0, r1, r2, r3, addr)                                             \
    asm volatile("ldmatrix.sync.aligned.m8n8.x4.shared.b16 {%0,%1,%2,%3}, [%4];"  \
                 : "=r"(r0), "=r"(r1), "=r"(r2), "=r"(r3) : "r"(addr))
#define LDSM_X4_T(r0, r1, r2, r3, addr)                                                \
    asm volatile("ldmatrix.sync.aligned.m8n8.x4.trans.shared.b16 {%0,%1,%2,%3}, [%4];" \
                 : "=r"(r0), "=r"(r1), "=r"(r2), "=r"(r3) : "r"(addr))
__device__ __forceinline__ void mma_bf16(float* c, const uint32_t* a, const uint32_t* b) {
    asm volatile(
        "mma.sync.aligned.m16n8k16.row.col.f32.bf16.bf16.f32 "
        "{%0,%1,%2,%3}, {%4,%5,%6,%7}, {%8,%9}, {%0,%1,%2,%3};"
        : "+f"(c[0]), "+f"(c[1]), "+f"(c[2]), "+f"(c[3])
        : "r"(a[0]), "r"(a[1]), "r"(a[2]), "r"(a[3]), "r"(b[0]), "r"(b[1]));
}
__device__ __forceinline__ uint32_t pack2(float x, float y) {
    __nv_bfloat162 t = __floats2bfloat162_rn(x, y);
    return *reinterpret_cast<uint32_t*>(&t);
}
__device__ __forceinline__ void split_pair(float x, float y, uint32_t& hi, uint32_t& lo) {
    const __nv_bfloat16 hx = __float2bfloat16_rn(x);
    const __nv_bfloat16 hy = __float2bfloat16_rn(y);
    __nv_bfloat162 hp; hp.x = hx; hp.y = hy;
    hi = *reinterpret_cast<uint32_t*>(&hp);
    lo = pack2(x - __bfloat162float(hx), y - __bfloat162float(hy));
}
__device__ __forceinline__ void split_store(__nv_bfloat16* hi, __nv_bfloat16* lo,
                                            size_t gi, float v0, float v1) {
    uint32_t h, l;
    split_pair(v0, v1, h, l);
    *(uint32_t*)(hi + gi) = h;
    *(uint32_t*)(lo + gi) = l;
}
// XOR swizzle: 16B segment s of row r lives at r*64 + ((s ^ ((r>>1)&3))<<4)
__device__ __forceinline__ uint32_t swz64(int r, int s) {
    return (uint32_t)(r * 64 + ((s ^ ((r >> 1) & 3)) << 4));
}

// ---------------------------------------------------------------------------
// merged weight convert: all 4 weight matrices in one launch
// ---------------------------------------------------------------------------
__global__ void cvt_all_kernel(const float* __restrict__ qkv_w, const float* __restrict__ proj_w,
                               const float* __restrict__ fc1_w, const float* __restrict__ fc2_w,
                               __nv_bfloat16* __restrict__ qw_hi, __nv_bfloat16* __restrict__ qw_lo,
                               __nv_bfloat16* __restrict__ pw_hi, __nv_bfloat16* __restrict__ pw_lo,
                               __nv_bfloat16* __restrict__ f1_hi, __nv_bfloat16* __restrict__ f1_lo,
                               __nv_bfloat16* __restrict__ f2_hi, __nv_bfloat16* __restrict__ f2_lo) {
    constexpr int N1 = 3 * C_ * C_ / 4, N2 = C_ * C_ / 4, N3 = HID_ * C_ / 4, N4 = C_ * HID_ / 4;
    int i = blockIdx.x * 256 + threadIdx.x;
    const float* src; __nv_bfloat16 *hi, *lo;
    if (i < N1)                 { src = qkv_w;  hi = qw_hi; lo = qw_lo; }
    else if ((i -= N1) < N2)    { src = proj_w; hi = pw_hi; lo = pw_lo; }
    else if ((i -= N2) < N3)    { src = fc1_w;  hi = f1_hi; lo = f1_lo; }
    else if ((i -= N3) < N4)    { src = fc2_w;  hi = f2_hi; lo = f2_lo; }
    else return;
    const float4 v = ((const float4*)src)[i];
    split_store(hi, lo, (size_t)i * 4, v.x, v.y);
    split_store(hi, lo, (size_t)i * 4 + 2, v.z, v.w);
}

// ---------------------------------------------------------------------------
// LayerNorm -> bf16 hi/lo planes
// ---------------------------------------------------------------------------
__global__ void ln_bf_kernel(const float* __restrict__ x, const float* __restrict__ w,
                             const float* __restrict__ bia,
                             __nv_bfloat16* __restrict__ hi, __nv_bfloat16* __restrict__ lo) {
    __shared__ float red[256];
    const int row = blockIdx.x;
    const int t = threadIdx.x;
    const float* xr = x + (size_t)row * C_;
    float v[3];
    float s = 0.f, s2 = 0.f;
#pragma unroll
    for (int j = 0; j < 3; j++) { v[j] = xr[t + 256 * j]; s += v[j]; s2 += v[j] * v[j]; }
    red[t] = s; __syncthreads();
    for (int o = 128; o > 0; o >>= 1) { if (t < o) red[t] += red[t + o]; __syncthreads(); }
    const float mean = red[0] * (1.f / C_);
    __syncthreads();
    red[t] = s2; __syncthreads();
    for (int o = 128; o > 0; o >>= 1) { if (t < o) red[t] += red[t + o]; __syncthreads(); }
    const float var = red[0] * (1.f / C_) - mean * mean;
    const float rstd = rsqrtf(var + 1e-5f);
#pragma unroll
    for (int j = 0; j < 3; j++) {
        const int c = t + 256 * j;
        const float y = (v[j] - mean) * rstd * w[c] + bia[c];
        const size_t gi = (size_t)row * C_ + c;
        const __nv_bfloat16 h = __float2bfloat16_rn(y);
        hi[gi] = h;
        lo[gi] = __float2bfloat16_rn(y - __bfloat162float(h));
    }
}

// ---------------------------------------------------------------------------
// Flash attention (validated in R6, unchanged)
// ---------------------------------------------------------------------------
__global__ void __launch_bounds__(256) flash_kernel(
    const __nv_bfloat16* __restrict__ QKVhi, const __nv_bfloat16* __restrict__ QKVlo,
    __nv_bfloat16* __restrict__ Ohi, __nv_bfloat16* __restrict__ Olo)
{
    constexpr int LDS = 72;
    constexpr uint32_t QPLANE  = 128 * LDS * 2;
    constexpr uint32_t KVPLANE = 64 * LDS * 2;
    constexpr uint32_t STAGE_B = 4 * KVPLANE;
    extern __shared__ __nv_bfloat16 sm[];
    const uint32_t qbase  = smem_u32(sm);
    const uint32_t kvbase = qbase + 2 * QPLANE;

    const int tid = threadIdx.x;
    const int wid = tid >> 5, lane = tid & 31;
    const int z = blockIdx.y, b = z / H_, hh = z % H_;
    const int row0 = blockIdx.x * 128;

    const __nv_bfloat16* qh = QKVhi + ((size_t)b * N_ + row0) * (3 * C_) + hh * D_;
    const __nv_bfloat16* ql = QKVlo + ((size_t)b * N_ + row0) * (3 * C_) + hh * D_;
    const __nv_bfloat16* kh = QKVhi + (size_t)b * N_ * (3 * C_) + C_ + hh * D_;
    const __nv_bfloat16* kl = QKVlo + (size_t)b * N_ * (3 * C_) + C_ + hh * D_;
    const __nv_bfloat16* vh = QKVhi + (size_t)b * N_ * (3 * C_) + 2 * C_ + hh * D_;
    const __nv_bfloat16* vl = QKVlo + (size_t)b * N_ * (3 * C_) + 2 * C_ + hh * D_;

#pragma unroll
    for (int i = 0; i < 16; i++) {
        const int u = i * 256 + tid;
        const int plane = u >> 11, r = (u >> 4) & 127, seg = u & 15;
        CP_ASYNC8(qbase + plane * QPLANE + (uint32_t)(r * 144 + seg * 8),
                  (plane ? ql : qh) + (size_t)r * (3 * C_) + seg * 4);
    }
    auto issueKV = [&](int c, int stage) {
        const int k0 = c * 64;
#pragma unroll
        for (int i = 0; i < 16; i++) {
            const int u = i * 256 + tid;
            const int plane = u >> 10, r = (u >> 4) & 63, seg = u & 15;
            const __nv_bfloat16* base =
                plane == 0 ? kh : plane == 1 ? kl : plane == 2 ? vh : vl;
            CP_ASYNC8(kvbase + stage * STAGE_B + plane * KVPLANE + (uint32_t)(r * 144 + seg * 8),
                      base + (size_t)(k0 + r) * (3 * C_) + seg * 4);
        }
    };
    issueKV(0, 0);
    CP_COMMIT();

    const int lar = lane & 15, lac = (lane >> 4) * 8;
    const int bq = lane >> 3, br = lane & 7;
    const int brow = (bq >> 1) * 8 + br, bcol = (bq & 1) * 8;

    uint32_t qf[2][4][4];
    float oacc[8][4] = {};
    float m_run0 = -1e30f, m_run1 = -1e30f;
    float l_run0 = 0.f, l_run1 = 0.f;

    for (int c = 0; c < 8; c++) {
        if (c + 1 < 8) issueKV(c + 1, (c + 1) & 1);
        CP_COMMIT();
        CP_WAIT1();
        __syncthreads();
        if (c == 0) {
#pragma unroll
            for (int pl = 0; pl < 2; pl++)
#pragma unroll
                for (int ks = 0; ks < 4; ks++)
                    LDSM_X4(qf[pl][ks][0], qf[pl][ks][1], qf[pl][ks][2], qf[pl][ks][3],
                            qbase + pl * QPLANE +
                            (uint32_t)(((wid * 16 + lar) * LDS + ks * 16 + lac) * 2));
        }
        const uint32_t st = kvbase + (c & 1) * STAGE_B;
        const uint32_t kHi = st, kLo = st + KVPLANE;
        const uint32_t vHi = st + 2 * KVPLANE, vLo = st + 3 * KVPLANE;

        float sacc[8][4] = {};
#pragma unroll
        for (int ks = 0; ks < 4; ks++) {
            uint32_t bh_[8][2], bl_[8][2];
#pragma unroll
            for (int nb = 0; nb < 4; nb++) {
                const uint32_t off = (uint32_t)(((nb * 16 + brow) * LDS + ks * 16 + bcol) * 2);
                LDSM_X4(bh_[2*nb][0], bh_[2*nb][1], bh_[2*nb+1][0], bh_[2*nb+1][1], kHi + off);
                LDSM_X4(bl_[2*nb][0], bl_[2*nb][1], bl_[2*nb+1][0], bl_[2*nb+1][1], kLo + off);
            }
#pragma unroll
            for (int nt = 0; nt < 8; nt++) {
                mma_bf16(sacc[nt], qf[0][ks], bh_[nt]);
                mma_bf16(sacc[nt], qf[0][ks], bl_[nt]);
                mma_bf16(sacc[nt], qf[1][ks], bh_[nt]);
            }
        }

        float mc0 = -1e30f, mc1 = -1e30f;
#pragma unroll
        for (int nt = 0; nt < 8; nt++) {
            mc0 = fmaxf(mc0, fmaxf(sacc[nt][0], sacc[nt][1]));
            mc1 = fmaxf(mc1, fmaxf(sacc[nt][2], sacc[nt][3]));
        }
        mc0 *= 0.125f; mc1 *= 0.125f;
#pragma unroll
        for (int o = 1; o <= 2; o <<= 1) {
            mc0 = fmaxf(mc0, __shfl_xor_sync(0xffffffffu, mc0, o));
            mc1 = fmaxf(mc1, __shfl_xor_sync(0xffffffffu, mc1, o));
        }
        const float mn0 = fmaxf(m_run0, mc0), mn1 = fmaxf(m_run1, mc1);
        const float a0 = __expf(m_run0 - mn0), a1 = __expf(m_run1 - mn1);
        m_run0 = mn0; m_run1 = mn1;
        float lc0 = 0.f, lc1 = 0.f;
#pragma unroll
        for (int nt = 0; nt < 8; nt++) {
            sacc[nt][0] = __expf(sacc[nt][0] * 0.125f - mn0);
            sacc[nt][1] = __expf(sacc[nt][1] * 0.125f - mn0);
            sacc[nt][2] = __expf(sacc[nt][2] * 0.125f - mn1);
            sacc[nt][3] = __expf(sacc[nt][3] * 0.125f - mn1);
            lc0 += sacc[nt][0] + sacc[nt][1];
            lc1 += sacc[nt][2] + sacc[nt][3];
            oacc[nt][0] *= a0; oacc[nt][1] *= a0;
            oacc[nt][2] *= a1; oacc[nt][3] *= a1;
        }
        l_run0 = l_run0 * a0 + lc0;
        l_run1 = l_run1 * a1 + lc1;

#pragma unroll
        for (int ks = 0; ks < 4; ks++) {
            const int t0 = 2 * ks, t1 = t0 + 1;
            uint32_t ph[4], plo_[4];
            split_pair(sacc[t0][0], sacc[t0][1], ph[0], plo_[0]);
            split_pair(sacc[t0][2], sacc[t0][3], ph[1], plo_[1]);
            split_pair(sacc[t1][0], sacc[t1][1], ph[2], plo_[2]);
            split_pair(sacc[t1][2], sacc[t1][3], ph[3], plo_[3]);
            uint32_t vh_[8][2], vl_[8][2];
#pragma unroll
            for (int nb = 0; nb < 4; nb++) {
                const uint32_t off =
                    (uint32_t)(((ks * 16 + (bq & 1) * 8 + br) * LDS + nb * 16 + (bq >> 1) * 8) * 2);
                LDSM_X4_T(vh_[2*nb][0], vh_[2*nb][1], vh_[2*nb+1][0], vh_[2*nb+1][1], vHi + off);
                LDSM_X4_T(vl_[2*nb][0], vl_[2*nb][1], vl_[2*nb+1][0], vl_[2*nb+1][1], vLo + off);
            }
#pragma unroll
            for (int nt = 0; nt < 8; nt++) {
                mma_bf16(oacc[nt], ph, vh_[nt]);
                mma_bf16(oacc[nt], ph, vl_[nt]);
                mma_bf16(oacc[nt], plo_, vh_[nt]);
            }
        }
        __syncthreads();
    }

#pragma unroll
    for (int o = 1; o <= 2; o <<= 1) {
        l_run0 += __shfl_xor_sync(0xffffffffu, l_run0, o);
        l_run1 += __shfl_xor_sync(0xffffffffu, l_run1, o);
    }
    const float inv0 = 1.f / l_run0, inv1 = 1.f / l_run1;
    const int rA = lane >> 2, colb = (lane & 3) * 2;
    const size_t obase = ((size_t)b * N_ + row0 + wid * 16) * C_ + hh * D_;
#pragma unroll
    for (int nt = 0; nt < 8; nt++) {
        split_store(Ohi, Olo, obase + (size_t)rA * C_ + nt * 8 + colb,
                    oacc[nt][0] * inv0, oacc[nt][1] * inv0);
        split_store(Ohi, Olo, obase + (size_t)(rA + 8) * C_ + nt * 8 + colb,
                    oacc[nt][2] * inv1, oacc[nt][3] * inv1);
    }
}

// ---------------------------------------------------------------------------
// bf16-split HMMA GEMM v5: 128-thread CTAs, block 128x128, warp tile 64x64,
// BK=32, XOR-swizzled smem (no padding), 3-stage ring, ONE barrier/chunk,
// 2 CTAs/SM.
// EPI: 0 -> hi/lo planes; 2 -> 2*(v+bias) fp32; 3 -> gelu(v+bias) planes;
//      4 -> v+bias+res fp32
// ---------------------------------------------------------------------------
template <int EPI>
__global__ void __launch_bounds__(128) mma_gemm5(
    const __nv_bfloat16* __restrict__ Ahi, const __nv_bfloat16* __restrict__ Alo,
    const __nv_bfloat16* __restrict__ Bhi, const __nv_bfloat16* __restrict__ Blo,
    const float* __restrict__ bias, const float* __restrict__ res,
    float* __restrict__ Cf, __nv_bfloat16* __restrict__ Chi, __nv_bfloat16* __restrict__ Clo,
    int K, int lda, int ldb, int ldc)
{
    constexpr uint32_t PLANE = 128 * 64;        // 8192 B (128 rows x 64 B)
    constexpr uint32_t STAGE_B = 4 * PLANE;     // 32768 B
    extern __shared__ __nv_bfloat16 sm[];
    const uint32_t sbase = smem_u32(sm);

    const int tid = threadIdx.x;
    const int wid = tid >> 5, lane = tid & 31;
    const int mOff = (wid & 1) * 64, nOff = (wid >> 1) * 64;

    const int row0 = blockIdx.y * 128, col0 = blockIdx.x * 128;
    const __nv_bfloat16* pl[4] = {
        Ahi + (size_t)row0 * lda, Alo + (size_t)row0 * lda,
        Bhi + (size_t)col0 * ldb, Blo + (size_t)col0 * ldb };

    auto issue = [&](int c, int stage) {
        const int k0 = c * 32;
        const uint32_t sst = sbase + stage * STAGE_B;
        // 4 planes x 128 rows x 4 segs of 16B, XOR-swizzled
#pragma unroll
        for (int i = 0; i < 16; i++) {
            const int u = i * 128 + tid;
            const int plane = u >> 9, r = (u >> 2) & 127, s = u & 3;
            const int ld = (plane < 2) ? lda : ldb;
            CP_ASYNC16(sst + plane * PLANE + swz64(r, s),
                       pl[plane] + (size_t)r * ld + k0 + s * 8);
        }
    };

    const int lar = lane & 15, lsg = lane >> 4;          // A: row-in-16, seg half
    const int bq = lane >> 3, br = lane & 7;
    const int brow = (bq >> 1) * 8 + br, bsg = bq & 1;   // B: row-in-16, seg half

    float acc[4][8][4] = {};

    const int chunks = K / 32;
    issue(0, 0); CP_COMMIT();
    issue(1, 1); CP_COMMIT();
    for (int c = 0; c < chunks; c++) {
        CP_WAIT1();
        __syncthreads();
        const uint32_t sst = sbase + (c % 3) * STAGE_B;
        const uint32_t aHiB = sst, aLoB = sst + PLANE;
        const uint32_t bHiB = sst + 2 * PLANE, bLoB = sst + 3 * PLANE;
#pragma unroll
        for (int kk = 0; kk < 32; kk += 16) {
            const int ksg = kk >> 3;   // 0 or 2
            uint32_t ah[4][4], bh_[8][2];
#pragma unroll
            for (int mi = 0; mi < 4; mi++) {
                const int R = mOff + mi * 16 + lar;
                LDSM_X4(ah[mi][0], ah[mi][1], ah[mi][2], ah[mi][3], aHiB + swz64(R, ksg + lsg));
            }
#pragma unroll
            for (int nb = 0; nb < 4; nb++) {
                const int R = nOff + nb * 16 + brow;
                LDSM_X4(bh_[2*nb][0], bh_[2*nb][1], bh_[2*nb+1][0], bh_[2*nb+1][1],
                        bHiB + swz64(R, ksg + bsg));
            }
            // term hh
#pragma unroll
            for (int mi = 0; mi < 4; mi++)
#pragma unroll
                for (int ni = 0; ni < 8; ni++)
                    mma_bf16(acc[mi][ni], ah[mi], bh_[ni]);
            // term hl: aHi x bLo
            {
                uint32_t bl_[8][2];
#pragma unroll
                for (int nb = 0; nb < 4; nb++) {
                    const int R = nOff + nb * 16 + brow;
                    LDSM_X4(bl_[2*nb][0], bl_[2*nb][1], bl_[2*nb+1][0], bl_[2*nb+1][1],
                            bLoB + swz64(R, ksg + bsg));
                }
#pragma unroll
                for (int mi = 0; mi < 4; mi++)
#pragma unroll
                    for (int ni = 0; ni < 8; ni++)
                        mma_bf16(acc[mi][ni], ah[mi], bl_[ni]);
            }
            // term lh: aLo x bHi
            {
                uint32_t al[4][4];
#pragma unroll
                for (int mi = 0; mi < 4; mi++) {
                    const int R = mOff + mi * 16 + lar;
                    LDSM_X4(al[mi][0], al[mi][1], al[mi][2], al[mi][3], aLoB + swz64(R, ksg + lsg));
                }
#pragma unroll
                for (int mi = 0; mi < 4; mi++)
#pragma unroll
                    for (int ni = 0; ni < 8; ni++)
                        mma_bf16(acc[mi][ni], al[mi], bh_[ni]);
            }
        }
        // prefetch chunk c+2 (its stage (c+2)%3 == (c-1)%3, freed by the
        // barrier above which proved all warps finished compute(c-1))
        if (c + 2 < chunks) issue(c + 2, (c + 2) % 3);
        CP_COMMIT();
    }

    // epilogue
#pragma unroll
    for (int mi = 0; mi < 4; mi++) {
#pragma unroll
        for (int ni = 0; ni < 8; ni++) {
#pragma unroll
            for (int h = 0; h < 2; h++) {
                const int r = row0 + mOff + mi * 16 + (lane >> 2) + h * 8;
                const int c = col0 + nOff + ni * 8 + (lane & 3) * 2;
                float v0 = acc[mi][ni][2 * h + 0];
                float v1 = acc[mi][ni][2 * h + 1];
                const size_t gi = (size_t)r * ldc + c;
                if (EPI == 0) {
                    split_store(Chi, Clo, gi, v0, v1);
                } else if (EPI == 2) {
                    *(float2*)(Cf + gi) = make_float2(2.f * (v0 + bias[c]), 2.f * (v1 + bias[c + 1]));
                } else if (EPI == 3) {
                    v0 += bias[c];  v1 += bias[c + 1];
                    v0 = 0.5f * v0 * (1.f + erff(v0 * 0.70710678118654752f));
                    v1 = 0.5f * v1 * (1.f + erff(v1 * 0.70710678118654752f));
                    split_store(Chi, Clo, gi, v0, v1);
                } else {  // EPI 4
                    v0 += bias[c] + res[gi];
                    v1 += bias[c + 1] + res[gi + 1];
                    *(float2*)(Cf + gi) = make_float2(v0, v1);
                }
            }
        }
    }
}

// ---------------------------------------------------------------------------
// Launch sequence
// ---------------------------------------------------------------------------
extern "C" void kernel_launch(void* const* d_in, const int* in_sizes, int n_in,
                              void* d_out, int out_size) {
    (void)in_sizes; (void)n_in; (void)out_size;
    const float* x      = (const float*)d_in[0];
    const float* ln1_w  = (const float*)d_in[1];
    const float* ln1_b  = (const float*)d_in[2];
    const float* qkv_w  = (const float*)d_in[3];
    const float* proj_w = (const float*)d_in[4];
    const float* proj_b = (const float*)d_in[5];
    const float* ln2_w  = (const float*)d_in[6];
    const float* ln2_b  = (const float*)d_in[7];
    const float* fc1_w  = (const float*)d_in[8];
    const float* fc1_b  = (const float*)d_in[9];
    const float* fc2_w  = (const float*)d_in[10];
    const float* fc2_b  = (const float*)d_in[11];
    float* out = (float*)d_out;

    float *xres;
    __nv_bfloat16 *h_hi, *h_lo, *qkv_hi, *qkv_lo, *o_hi, *o_lo, *f1_hi, *f1_lo;
    __nv_bfloat16 *qw_hi, *qw_lo, *pw_hi, *pw_lo, *f1w_hi, *f1w_lo, *f2w_hi, *f2w_lo;
    cudaGetSymbolAddress((void**)&xres,   g_xres);
    cudaGetSymbolAddress((void**)&h_hi,   g_h_hi);   cudaGetSymbolAddress((void**)&h_lo,   g_h_lo);
    cudaGetSymbolAddress((void**)&qkv_hi, g_qkv_hi); cudaGetSymbolAddress((void**)&qkv_lo, g_qkv_lo);
    cudaGetSymbolAddress((void**)&o_hi,   g_o_hi);   cudaGetSymbolAddress((void**)&o_lo,   g_o_lo);
    cudaGetSymbolAddress((void**)&f1_hi,  g_f1_hi);  cudaGetSymbolAddress((void**)&f1_lo,  g_f1_lo);
    cudaGetSymbolAddress((void**)&qw_hi,  g_qkvw_hi);  cudaGetSymbolAddress((void**)&qw_lo,  g_qkvw_lo);
    cudaGetSymbolAddress((void**)&pw_hi,  g_projw_hi); cudaGetSymbolAddress((void**)&pw_lo,  g_projw_lo);
    cudaGetSymbolAddress((void**)&f1w_hi, g_fc1w_hi);  cudaGetSymbolAddress((void**)&f1w_lo, g_fc1w_lo);
    cudaGetSymbolAddress((void**)&f2w_hi, g_fc2w_hi);  cudaGetSymbolAddress((void**)&f2w_lo, g_fc2w_lo);

    constexpr int SMEM_GEMM  = 3 * 4 * 128 * 64;                         // 98304
    constexpr int SMEM_FLASH = 2 * 128 * 72 * 2 + 2 * 4 * 64 * 72 * 2;   // 110592
    cudaFuncSetAttribute(mma_gemm5<0>, cudaFuncAttributeMaxDynamicSharedMemorySize, SMEM_GEMM);
    cudaFuncSetAttribute(mma_gemm5<2>, cudaFuncAttributeMaxDynamicSharedMemorySize, SMEM_GEMM);
    cudaFuncSetAttribute(mma_gemm5<3>, cudaFuncAttributeMaxDynamicSharedMemorySize, SMEM_GEMM);
    cudaFuncSetAttribute(mma_gemm5<4>, cudaFuncAttributeMaxDynamicSharedMemorySize, SMEM_GEMM);
    cudaFuncSetAttribute(flash_kernel, cudaFuncAttributeMaxDynamicSharedMemorySize, SMEM_FLASH);

    // 0. pre-split all weights to bf16 hi/lo (single launch)
    constexpr int CVT_TOTAL = (3 * C_ * C_ + C_ * C_ + HID_ * C_ + C_ * HID_) / 4;
    cvt_all_kernel<<<(CVT_TOTAL + 255) / 256, 256>>>(
        qkv_w, proj_w, fc1_w, fc2_w,
        qw_hi, qw_lo, pw_hi, pw_lo, f1w_hi, f1w_lo, f2w_hi, f2w_lo);

    // 1. LN1 -> h planes
    ln_bf_kernel<<<M_, 256>>>(x, ln1_w, ln1_b, h_hi, h_lo);
    // 2. QKV -> qkv planes
    mma_gemm5<0><<<dim3(18, 128, 1), 128, SMEM_GEMM>>>(
        h_hi, h_lo, qw_hi, qw_lo, nullptr, nullptr, nullptr, qkv_hi, qkv_lo,
        C_, C_, C_, 3 * C_);
    // 3-5. flash attention -> o planes
    flash_kernel<<<dim3(4, BH_), 256, SMEM_FLASH>>>(qkv_hi, qkv_lo, o_hi, o_lo);
    // 6. xres = 2*(o @ proj_w^T + proj_b)
    mma_gemm5<2><<<dim3(6, 128, 1), 128, SMEM_GEMM>>>(
        o_hi, o_lo, pw_hi, pw_lo, proj_b, nullptr, xres, nullptr, nullptr,
        C_, C_, C_, C_);
    // 7. LN2 -> h planes
    ln_bf_kernel<<<M_, 256>>>(xres, ln2_w, ln2_b, h_hi, h_lo);
    // 8. fc1 + GELU -> f1 planes
    mma_gemm5<3><<<dim3(24, 128, 1), 128, SMEM_GEMM>>>(
        h_hi, h_lo, f1w_hi, f1w_lo, fc1_b, nullptr, nullptr, f1_hi, f1_lo,
        C_, C_, C_, HID_);
    // 9. out = xres + f1 @ fc2_w^T + fc2_b
    mma_gemm5<4><<<dim3(6, 128, 1), 128, SMEM_GEMM>>>(
        f1_hi, f1_lo, f2w_hi, f2w_lo, fc2_b, xres, out, nullptr, nullptr,
        HID_, HID_, HID_, C_);
}